// round 7
// baseline (speedup 1.0000x reference)
#include <cuda_runtime.h>
#include <cuda_bf16.h>

// MarginRankingLoss: x[V=4096, C=128, T=128] fp32, target[V,C] int64 -> scalar.
// loss = ( sum_{v,c,t} max(0, x - x[target] + 0.5) - 0.5*V*C ) / (V*C*(T-1))
// (the target position always contributes exactly 0.5, subtracted analytically)
//
// 2-kernel graph: main -> finalize.
// Main: blocked 32 rows/warp (full coverage), coalesced target prefetch,
// MLP-8 unroll, streaming loads. Each block writes its partial to a DISTINCT
// address (g_partials[blockIdx.x], plain STG.cg) -- removes the single-address
// L2-atomic serialization tail (~27-32 cyc/op x 2048 blocks) of the atomicAdd
// version. Finalize: 256 threads reduce 2048 partials in double, write out.
// Partials are overwritten every call => deterministic across graph replays.

#define NROWS (4096 * 128)   // V*C = 524288
#define TDIM 128
#define NBLOCKS 2048
#define NTHREADS 256
#define ROWS_PER_WARP 32     // NROWS / (NBLOCKS * NTHREADS / 32)

__device__ float g_partials[NBLOCKS];

__global__ __launch_bounds__(NTHREADS) void mrl_main_kernel(
    const float4* __restrict__ x,          // [NROWS * 32] float4 view
    const long long* __restrict__ target)  // [NROWS]
{
    const int lane = threadIdx.x & 31;
    const int warp = (blockIdx.x * NTHREADS + threadIdx.x) >> 5;
    const int base = warp * ROWS_PER_WARP;

    // One coalesced 256B load fetches this warp's 32 int64 targets.
    const int tt = (int)target[base + lane];

    float acc = 0.0f;

    #pragma unroll 8
    for (int i = 0; i < ROWS_PER_WARP; i++) {
        const float4 v = __ldcs(&x[(base + i) * 32 + lane]);
        const int t = __shfl_sync(0xffffffffu, tt, i);

        // extract x[row][t]: lane t>>2 holds it in element t&3
        float p = (t & 2) ? ((t & 1) ? v.w : v.z)
                          : ((t & 1) ? v.y : v.x);
        const float pos = __shfl_sync(0xffffffffu, p, t >> 2);

        const float b = 0.5f - pos;
        acc += fmaxf(v.x + b, 0.0f) + fmaxf(v.y + b, 0.0f)
             + fmaxf(v.z + b, 0.0f) + fmaxf(v.w + b, 0.0f);
    }

    // warp reduce
    #pragma unroll
    for (int o = 16; o; o >>= 1)
        acc += __shfl_xor_sync(0xffffffffu, acc, o);

    __shared__ float smem[NTHREADS / 32];
    if (lane == 0) smem[threadIdx.x >> 5] = acc;
    __syncthreads();

    if (threadIdx.x == 0) {
        float bsum = 0.0f;
        #pragma unroll
        for (int w = 0; w < NTHREADS / 32; w++) bsum += smem[w];
        __stcg(&g_partials[blockIdx.x], bsum);   // distinct addr: no contention
    }
}

__global__ __launch_bounds__(NTHREADS) void mrl_finalize_kernel(float* __restrict__ out) {
    const int lane = threadIdx.x & 31;

    double d = 0.0;
    #pragma unroll
    for (int i = threadIdx.x; i < NBLOCKS; i += NTHREADS)
        d += (double)__ldcg(&g_partials[i]);

    #pragma unroll
    for (int o = 16; o; o >>= 1)
        d += __shfl_xor_sync(0xffffffffu, d, o);

    __shared__ double dsm[NTHREADS / 32];
    if (lane == 0) dsm[threadIdx.x >> 5] = d;
    __syncthreads();

    if (threadIdx.x == 0) {
        double tot = 0.0;
        #pragma unroll
        for (int w = 0; w < NTHREADS / 32; w++) tot += dsm[w];
        // subtract the target-position hinge (exactly 0.5 per row), then mean
        const double corrected = tot - 0.5 * (double)NROWS;
        out[0] = (float)(corrected / ((double)NROWS * (double)(TDIM - 1)));
    }
}

extern "C" void kernel_launch(void* const* d_in, const int* in_sizes, int n_in,
                              void* d_out, int out_size) {
    const float4*    x   = (const float4*)d_in[0];
    const long long* tgt = (const long long*)d_in[1];
    float*           out = (float*)d_out;

    mrl_main_kernel<<<NBLOCKS, NTHREADS>>>(x, tgt);
    mrl_finalize_kernel<<<1, NTHREADS>>>(out);
}

// round 8
// speedup vs baseline: 1.1898x; 1.1898x over previous
#include <cuda_runtime.h>
#include <cuda_bf16.h>

// MarginRankingLoss: x[V=4096, C=128, T=128] fp32, target[V,C] int64 -> scalar.
// loss = ( sum_{v,c,t} max(0, x - x[target] + 0.5) - 0.5*V*C ) / (V*C*(T-1))
// (the target position always contributes exactly 0.5, subtracted analytically)
//
// ONE-WAVE persistent grid: launch_bounds(256,5) x 148 SMs = 740 blocks = one
// full wave (old 2048-block grid ran 1.73 waves; the 2nd wave filled only 73%
// of slots -> ~73% BW for the back half, matching measured DRAM=70%).
// Warps grid-stride over 8-row chunks (65536 chunks / 5920 warps ~ 11 each,
// imbalance <= 4 KiB). Chunk fully unrolled -> 8 LDG.128 in flight per warp.
// Reduction: block atomicAdd(double) (proven fine; R7 showed de-atomicizing
// REGRESSED), finalize<<<1,1>>> reads + resets g_mrl_sum (replay-invariant).

#define NROWS  (4096 * 128)   // V*C = 524288
#define TDIM   128
#define NSM    148
#define CTASM  5
#define NBLOCKS (NSM * CTASM) // 740 = exactly one wave
#define NTHREADS 256
#define CHUNK  8
#define NCHUNK (NROWS / CHUNK) // 65536

__device__ double g_mrl_sum;   // zero-init; finalize restores 0 each call

__global__ __launch_bounds__(NTHREADS, CTASM) void mrl_main_kernel(
    const float4* __restrict__ x,          // [NROWS * 32] float4 view
    const long long* __restrict__ target)  // [NROWS]
{
    const int lane  = threadIdx.x & 31;
    const int warp  = (blockIdx.x * NTHREADS + threadIdx.x) >> 5;
    const int nwarp = (NBLOCKS * NTHREADS) >> 5;   // 5920

    float acc = 0.0f;

    for (int c = warp; c < NCHUNK; c += nwarp) {
        const int base = c * CHUNK;

        // lanes 0-7 fetch this chunk's 8 int64 targets (one 64B transaction)
        int tt = 0;
        if (lane < CHUNK) tt = (int)target[base + lane];

        #pragma unroll
        for (int i = 0; i < CHUNK; i++) {
            const float4 v = __ldcs(&x[(base + i) * 32 + lane]);
            const int t = __shfl_sync(0xffffffffu, tt, i);

            // extract x[row][t]: lane t>>2 holds it in element t&3
            float p = (t & 2) ? ((t & 1) ? v.w : v.z)
                              : ((t & 1) ? v.y : v.x);
            const float pos = __shfl_sync(0xffffffffu, p, t >> 2);

            const float b = 0.5f - pos;
            acc += fmaxf(v.x + b, 0.0f) + fmaxf(v.y + b, 0.0f)
                 + fmaxf(v.z + b, 0.0f) + fmaxf(v.w + b, 0.0f);
        }
    }

    // warp reduce
    #pragma unroll
    for (int o = 16; o; o >>= 1)
        acc += __shfl_xor_sync(0xffffffffu, acc, o);

    __shared__ float smem[NTHREADS / 32];
    if (lane == 0) smem[threadIdx.x >> 5] = acc;
    __syncthreads();

    if (threadIdx.x == 0) {
        float bsum = 0.0f;
        #pragma unroll
        for (int w = 0; w < NTHREADS / 32; w++) bsum += smem[w];
        atomicAdd(&g_mrl_sum, (double)bsum);
    }
}

__global__ void mrl_finalize_kernel(float* __restrict__ out) {
    // subtract the target-position hinge (exactly 0.5 per row), then mean
    const double corrected = g_mrl_sum - 0.5 * (double)NROWS;
    out[0] = (float)(corrected / ((double)NROWS * (double)(TDIM - 1)));
    g_mrl_sum = 0.0;   // restore initial state for the next call/replay
}

extern "C" void kernel_launch(void* const* d_in, const int* in_sizes, int n_in,
                              void* d_out, int out_size) {
    const float4*    x   = (const float4*)d_in[0];
    const long long* tgt = (const long long*)d_in[1];
    float*           out = (float*)d_out;

    mrl_main_kernel<<<NBLOCKS, NTHREADS>>>(x, tgt);
    mrl_finalize_kernel<<<1, 1>>>(out);
}